// round 8
// baseline (speedup 1.0000x reference)
#include <cuda_runtime.h>
#include <cuda_bf16.h>
#include <cstdint>

#define BI 4
#define CI 64
#define HI 128
#define WI 128
#define HWI (HI*WI)
#define JO 18
#define JP 20
#define CO 64
#define KKN 9
#define TPX 128
#define PADQ 129   // float4 row stride of sample tile

typedef unsigned long long u64;

__device__ __forceinline__ void ffma2(u64 &d, u64 a, u64 b) {
    asm("fma.rn.f32x2 %0, %1, %2, %0;" : "+l"(d) : "l"(a), "l"(b));
}
__device__ __forceinline__ u64 pack2(float lo, float hi) {
    u64 r; asm("mov.b64 %0, {%1, %2};" : "=l"(r) : "f"(lo), "f"(hi)); return r;
}
__device__ __forceinline__ float2 unpack2(u64 v) {
    float2 r; asm("mov.b64 {%0, %1}, %2;" : "=f"(r.x), "=f"(r.y) : "l"(v)); return r;
}

// Scratch: offsets [b][j][h][w]; NHWC copy of x; transposed def-weights [kk][c][o]
__device__ float g_off[BI*JO*HWI];
__device__ float g_xt[BI*HWI*CI];     // 16 MB, [b][p][c]
__device__ float g_wt[KKN*CI*CO];

// ---------------------------------------------------------------------------
// Prep A: NCHW -> NHWC transpose of x (tiled, conflict-free)
// ---------------------------------------------------------------------------
__global__ void transpose_x_kernel(const float* __restrict__ x) {
    __shared__ float t[32][33];
    int b  = blockIdx.z;
    int c0 = blockIdx.y * 32;
    int p0 = blockIdx.x * 32;
    int tx = threadIdx.x, ty = threadIdx.y;   // block (32,8)
    const float* xb = x + (b*CI + c0)*HWI + p0;
    #pragma unroll
    for (int j = 0; j < 4; j++)
        t[ty + 8*j][tx] = xb[(ty + 8*j)*HWI + tx];
    __syncthreads();
    float* ob = g_xt + ((size_t)b*HWI + p0)*CI + c0;
    #pragma unroll
    for (int j = 0; j < 4; j++)
        ob[(ty + 8*j)*CI + tx] = t[tx][ty + 8*j];
}

// ---------------------------------------------------------------------------
// Prep B: transpose w_def [o][c][kk] -> g_wt [kk][c][o]
// ---------------------------------------------------------------------------
__global__ void transpose_wdef_kernel(const float* __restrict__ w_def) {
    int i = blockIdx.x * blockDim.x + threadIdx.x;
    if (i < KKN*CI*CO) {
        int o = i & 63; int rest = i >> 6; int c = rest % CI; int kk = rest / CI;
        g_wt[i] = w_def[(o*CI + c)*KKN + kk];
    }
}

// ---------------------------------------------------------------------------
// Kernel 1: offset conv, 1 pixel/thread, packed f32x2 accumulators.
// ---------------------------------------------------------------------------
__global__ __launch_bounds__(256, 4)
void offset_conv_kernel(const float* __restrict__ x,
                        const float* __restrict__ w_off,
                        const float* __restrict__ b_off) {
    __shared__ __align__(16) float ws[KKN*CI*JP];
    int tid = threadIdx.x;
    for (int i = tid; i < KKN*CI*JO; i += blockDim.x) {
        int j = i % JO; int rest = i / JO; int c = rest % CI; int tap = rest / CI;
        ws[(tap*CI + c)*JP + j] = w_off[(j*CI + c)*KKN + tap];
    }
    __syncthreads();

    int p = blockIdx.x * blockDim.x + tid;
    int b = p >> 14, rem = p & (HWI-1);
    int h = rem >> 7, w = rem & (WI-1);
    const float* xb = x + b*CI*HWI;

    u64 acc[9];
    #pragma unroll
    for (int q = 0; q < 9; q++)
        acc[q] = pack2(__ldg(&b_off[2*q]), __ldg(&b_off[2*q+1]));

    for (int tap = 0; tap < KKN; tap++) {
        int ky = tap / 3, kx = tap % 3;
        int y = h - 1 + ky, xx = w - 1 + kx;
        bool v = (y >= 0) & (y < HI) & (xx >= 0) & (xx < WI);
        int idx = y*WI + xx;
        const float* wrow = ws + tap*CI*JP;
        for (int c = 0; c < CI; c++) {
            float a = v ? __ldg(xb + c*HWI + idx) : 0.f;
            u64 a2 = pack2(a, a);
            const ulonglong2* w4 = (const ulonglong2*)(wrow + c*JP);
            #pragma unroll
            for (int q = 0; q < 4; q++) {
                ulonglong2 wv = w4[q];
                ffma2(acc[2*q+0], a2, wv.x);
                ffma2(acc[2*q+1], a2, wv.y);
            }
            u64 w8 = *(const u64*)(wrow + c*JP + 16);
            ffma2(acc[8], a2, w8);
        }
    }
    #pragma unroll
    for (int q = 0; q < 9; q++) {
        float2 vv = unpack2(acc[q]);
        g_off[(b*JO + 2*q+0)*HWI + rem] = vv.x;
        g_off[(b*JO + 2*q+1)*HWI + rem] = vv.y;
    }
}

// ---------------------------------------------------------------------------
// Kernel 2: cooperative NHWC sampling + register-blocked GEMM.
// Block = 128 threads = one image row (128 px).
// Sampling: 16 lanes per pixel; each lane LDG.128s 4 channels of each of the
//   4 bilinear neighbors from NHWC g_xt, blends, STS.128 into S4[cquad][px].
// GEMM: 8o x 8px FFMA2 tile per thread (two px-quad halves), weights via
//   uniform LDG from g_wt, samples via broadcast LDS.128 from S4.
// ---------------------------------------------------------------------------
__global__ __launch_bounds__(128, 4)
void deform_main_kernel(float* __restrict__ out) {
    __shared__ __align__(16) float4 S4[16*PADQ];   // 33,024 B
    __shared__ float4 wts[TPX];                    // bilinear weights per px
    __shared__ int4   idx4[TPX];                   // neighbor indices per px

    int tid = threadIdx.x;
    int wid = tid >> 5, lid = tid & 31;
    int l = lid & 15, half = lid >> 4;
    int blk = blockIdx.x;
    int b = blk >> 7;
    int h = blk & 127;
    int rowoff = h * WI;
    int w = tid;
    const float* offp = g_off + b*JO*HWI + rowoff + w;
    const float* xtb = g_xt + (size_t)b*HWI*CI + 4*l;

    int o0 = (tid >> 4) * 8;   // 8 output channels
    int qb = tid & 15;         // px quads at 4qb and 64+4qb

    u64 acc[8][4];
    #pragma unroll
    for (int o = 0; o < 8; o++)
        #pragma unroll
        for (int q = 0; q < 4; q++) acc[o][q] = 0ULL;

    for (int kk = 0; kk < KKN; kk++) {
        __syncthreads();   // previous GEMM done with S4 / sampling done with params

        // --- own-pixel bilinear setup -> params in smem ---
        float dy = __ldg(offp + (2*kk + 0)*HWI);
        float dx = __ldg(offp + (2*kk + 1)*HWI);
        float py = (float)(h - 1 + kk / 3) + dy;
        float px = (float)(w - 1 + kk % 3) + dx;
        float y0f = floorf(py), x0f = floorf(px);
        float fy = py - y0f, fx = px - x0f;
        int y0 = (int)y0f, x0 = (int)x0f;
        int y1 = y0 + 1,   x1 = x0 + 1;
        float vy0 = (y0 >= 0 && y0 < HI) ? 1.f : 0.f;
        float vy1 = (y1 >= 0 && y1 < HI) ? 1.f : 0.f;
        float vx0 = (x0 >= 0 && x0 < WI) ? 1.f : 0.f;
        float vx1 = (x1 >= 0 && x1 < WI) ? 1.f : 0.f;
        float w00 = (1.f - fy) * (1.f - fx) * vy0 * vx0;
        float w01 = (1.f - fy) * fx         * vy0 * vx1;
        float w10 = fy         * (1.f - fx) * vy1 * vx0;
        float w11 = fy         * fx         * vy1 * vx1;
        int y0c = min(max(y0, 0), HI-1), y1c = min(max(y1, 0), HI-1);
        int x0c = min(max(x0, 0), WI-1), x1c = min(max(x1, 0), WI-1);
        wts[tid]  = make_float4(w00, w01, w10, w11);
        idx4[tid] = make_int4(y0c*WI + x0c, y0c*WI + x1c,
                              y1c*WI + x0c, y1c*WI + x1c);
        __syncthreads();

        // --- cooperative sampling: warp covers px [wid*32, wid*32+32) ---
        #pragma unroll 4
        for (int t = 0; t < 16; t++) {
            int p = wid*32 + 2*t + half;
            float4 wv = wts[p];
            int4 ii = idx4[p];
            float4 n00 = __ldg((const float4*)(xtb + (size_t)ii.x*CI));
            float4 n01 = __ldg((const float4*)(xtb + (size_t)ii.y*CI));
            float4 n10 = __ldg((const float4*)(xtb + (size_t)ii.z*CI));
            float4 n11 = __ldg((const float4*)(xtb + (size_t)ii.w*CI));
            float4 s;
            s.x = wv.x*n00.x + wv.y*n01.x + wv.z*n10.x + wv.w*n11.x;
            s.y = wv.x*n00.y + wv.y*n01.y + wv.z*n10.y + wv.w*n11.y;
            s.z = wv.x*n00.z + wv.y*n01.z + wv.z*n10.z + wv.w*n11.z;
            s.w = wv.x*n00.w + wv.y*n01.w + wv.z*n10.w + wv.w*n11.w;
            S4[l*PADQ + p] = s;
        }
        __syncthreads();

        // --- GEMM: acc[8o][8px] += W[o][c] * S[c][px] ---
        const float* wk = g_wt + kk*CI*CO + o0;
        #pragma unroll 2
        for (int q = 0; q < 16; q++) {
            const float4* srow = S4 + q*PADQ;
            // half A: px 4qb..4qb+3
            {
                float4 sa0 = srow[4*qb + 0], sa1 = srow[4*qb + 1];
                float4 sa2 = srow[4*qb + 2], sa3 = srow[4*qb + 3];
                const float* s0 = (const float*)&sa0;
                const float* s1 = (const float*)&sa1;
                const float* s2 = (const float*)&sa2;
                const float* s3 = (const float*)&sa3;
                #pragma unroll
                for (int j = 0; j < 4; j++) {
                    int c = 4*q + j;
                    const float* wr = wk + (c << 6);
                    float4 wa = __ldg((const float4*)(wr));
                    float4 wb = __ldg((const float4*)(wr + 4));
                    u64 sp0 = pack2(s0[j], s1[j]);
                    u64 sp1 = pack2(s2[j], s3[j]);
                    u64 w2[8];
                    w2[0] = pack2(wa.x, wa.x); w2[1] = pack2(wa.y, wa.y);
                    w2[2] = pack2(wa.z, wa.z); w2[3] = pack2(wa.w, wa.w);
                    w2[4] = pack2(wb.x, wb.x); w2[5] = pack2(wb.y, wb.y);
                    w2[6] = pack2(wb.z, wb.z); w2[7] = pack2(wb.w, wb.w);
                    #pragma unroll
                    for (int o = 0; o < 8; o++) {
                        ffma2(acc[o][0], sp0, w2[o]);
                        ffma2(acc[o][1], sp1, w2[o]);
                    }
                }
            }
            // half B: px 64+4qb..64+4qb+3
            {
                float4 sa0 = srow[64 + 4*qb + 0], sa1 = srow[64 + 4*qb + 1];
                float4 sa2 = srow[64 + 4*qb + 2], sa3 = srow[64 + 4*qb + 3];
                const float* s0 = (const float*)&sa0;
                const float* s1 = (const float*)&sa1;
                const float* s2 = (const float*)&sa2;
                const float* s3 = (const float*)&sa3;
                #pragma unroll
                for (int j = 0; j < 4; j++) {
                    int c = 4*q + j;
                    const float* wr = wk + (c << 6);
                    float4 wa = __ldg((const float4*)(wr));
                    float4 wb = __ldg((const float4*)(wr + 4));
                    u64 sp2 = pack2(s0[j], s1[j]);
                    u64 sp3 = pack2(s2[j], s3[j]);
                    u64 w2[8];
                    w2[0] = pack2(wa.x, wa.x); w2[1] = pack2(wa.y, wa.y);
                    w2[2] = pack2(wa.z, wa.z); w2[3] = pack2(wa.w, wa.w);
                    w2[4] = pack2(wb.x, wb.x); w2[5] = pack2(wb.y, wb.y);
                    w2[6] = pack2(wb.z, wb.z); w2[7] = pack2(wb.w, wb.w);
                    #pragma unroll
                    for (int o = 0; o < 8; o++) {
                        ffma2(acc[o][2], sp2, w2[o]);
                        ffma2(acc[o][3], sp3, w2[o]);
                    }
                }
            }
        }
    }

    // write out: thread's px quads at 4qb and 64+4qb
    #pragma unroll
    for (int o = 0; o < 8; o++) {
        float* orow = out + (b*CO + o0 + o)*HWI + rowoff;
        #pragma unroll
        for (int j = 0; j < 2; j++) {
            float2 v0 = unpack2(acc[o][2*j+0]);
            float2 v1 = unpack2(acc[o][2*j+1]);
            float4 v = make_float4(v0.x, v0.y, v1.x, v1.y);
            *(float4*)(orow + 4*qb + 64*j) = v;
        }
    }
}

// ---------------------------------------------------------------------------
// Launch
// Inputs: x (4*64*128*128), w_off (18*64*9), b_off (18), w_def (64*64*9)
// Output: (4, 64, 128, 128) fp32
// ---------------------------------------------------------------------------
extern "C" void kernel_launch(void* const* d_in, const int* in_sizes, int n_in,
                              void* d_out, int out_size) {
    const float* x     = (const float*)d_in[0];
    const float* w_off = (const float*)d_in[1];
    const float* b_off = (const float*)d_in[2];
    const float* w_def = (const float*)d_in[3];
    float* out = (float*)d_out;

    const int total_px = BI*HWI;  // 65536

    dim3 tg(HWI/32, CI/32, BI);
    transpose_x_kernel<<<tg, dim3(32, 8)>>>(x);
    transpose_wdef_kernel<<<(KKN*CI*CO + 255)/256, 256>>>(w_def);
    offset_conv_kernel<<<total_px/256, 256>>>(x, w_off, b_off);
    deform_main_kernel<<<total_px/TPX, TPX>>>(out);
}

// round 9
// speedup vs baseline: 1.0774x; 1.0774x over previous
#include <cuda_runtime.h>
#include <cuda_bf16.h>
#include <cstdint>

#define BI 4
#define CI 64
#define HI 128
#define WI 128
#define HWI (HI*WI)
#define JO 18
#define JP 20
#define CO 64
#define KKN 9

typedef unsigned long long u64;

__device__ __forceinline__ void ffma2(u64 &d, u64 a, u64 b) {
    asm("fma.rn.f32x2 %0, %1, %2, %0;" : "+l"(d) : "l"(a), "l"(b));
}
__device__ __forceinline__ u64 pack2(float lo, float hi) {
    u64 r; asm("mov.b64 %0, {%1, %2};" : "=l"(r) : "f"(lo), "f"(hi)); return r;
}
__device__ __forceinline__ float2 unpack2(u64 v) {
    float2 r; asm("mov.b64 {%0, %1}, %2;" : "=f"(r.x), "=f"(r.y) : "l"(v)); return r;
}

// Scratch: offsets [b][j][h][w]; transposed def-weights [kk][c][o]
__device__ float g_off[BI*JO*HWI];
__device__ float g_wt[KKN*CI*CO];

// ---------------------------------------------------------------------------
// Prep: transpose w_def [o][c][kk] -> g_wt [kk][c][o]
// ---------------------------------------------------------------------------
__global__ void transpose_wdef_kernel(const float* __restrict__ w_def) {
    int i = blockIdx.x * blockDim.x + threadIdx.x;
    if (i < KKN*CI*CO) {
        int o = i & 63; int rest = i >> 6; int c = rest % CI; int kk = rest / CI;
        g_wt[i] = w_def[(o*CI + c)*KKN + kk];
    }
}

// ---------------------------------------------------------------------------
// Kernel 1: offset conv, 1 pixel/thread, packed f32x2 accumulators.
// ---------------------------------------------------------------------------
__global__ __launch_bounds__(256, 4)
void offset_conv_kernel(const float* __restrict__ x,
                        const float* __restrict__ w_off,
                        const float* __restrict__ b_off) {
    __shared__ __align__(16) float ws[KKN*CI*JP];
    int tid = threadIdx.x;
    for (int i = tid; i < KKN*CI*JO; i += blockDim.x) {
        int j = i % JO; int rest = i / JO; int c = rest % CI; int tap = rest / CI;
        ws[(tap*CI + c)*JP + j] = w_off[(j*CI + c)*KKN + tap];
    }
    __syncthreads();

    int p = blockIdx.x * blockDim.x + tid;
    int b = p >> 14, rem = p & (HWI-1);
    int h = rem >> 7, w = rem & (WI-1);
    const float* xb = x + b*CI*HWI;

    u64 acc[9];
    #pragma unroll
    for (int q = 0; q < 9; q++)
        acc[q] = pack2(__ldg(&b_off[2*q]), __ldg(&b_off[2*q+1]));

    for (int tap = 0; tap < KKN; tap++) {
        int ky = tap / 3, kx = tap % 3;
        int y = h - 1 + ky, xx = w - 1 + kx;
        bool v = (y >= 0) & (y < HI) & (xx >= 0) & (xx < WI);
        int idx = y*WI + xx;
        const float* wrow = ws + tap*CI*JP;
        for (int c = 0; c < CI; c++) {
            float a = v ? __ldg(xb + c*HWI + idx) : 0.f;
            u64 a2 = pack2(a, a);
            const ulonglong2* w4 = (const ulonglong2*)(wrow + c*JP);
            #pragma unroll
            for (int q = 0; q < 4; q++) {
                ulonglong2 wv = w4[q];
                ffma2(acc[2*q+0], a2, wv.x);
                ffma2(acc[2*q+1], a2, wv.y);
            }
            u64 w8 = *(const u64*)(wrow + c*JP + 16);
            ffma2(acc[8], a2, w8);
        }
    }
    #pragma unroll
    for (int q = 0; q < 9; q++) {
        float2 vv = unpack2(acc[q]);
        g_off[(b*JO + 2*q+0)*HWI + rem] = vv.x;
        g_off[(b*JO + 2*q+1)*HWI + rem] = vv.y;
    }
}

// ---------------------------------------------------------------------------
// Kernel 2: half-row per block (64 px), 128 threads.
// Sampling: 2 threads per px, 32 channels each -> S[c][64] (16 KB).
// GEMM: thread tile 8o x 4px; samples via 2-wf LDS.128, weights via
//   uniform LDG.128 from pre-transposed g_wt. acc = 16 u64.
// ---------------------------------------------------------------------------
__global__ __launch_bounds__(128, 5)
void deform_main_kernel(const float* __restrict__ x,
                        float* __restrict__ out) {
    __shared__ __align__(16) float S[CI*64];   // 16 KB

    int tid = threadIdx.x;
    int blk = blockIdx.x;        // 1024 blocks
    int b = blk >> 8;
    int r = blk & 255;           // half-row index
    int h = r >> 1;
    int colbase = (r & 1) * 64;
    int rowoff = h*WI + colbase;
    const float* xb = x + b*CI*HWI;

    int spx = tid & 63;          // sampling pixel (local 0..63)
    int chalf = tid >> 6;        // 0/1 -> channel range
    int w = colbase + spx;
    const float* offp = g_off + b*JO*HWI + h*WI + w;
    const float* xch = xb + (chalf*32)*HWI;
    float* Srow = S + (chalf*32)*64 + spx;

    int o0 = (tid >> 4) * 8;     // 8 output channels
    int qb = tid & 15;           // px quad at 4*qb

    u64 acc[8][2];
    #pragma unroll
    for (int o = 0; o < 8; o++) { acc[o][0] = 0ULL; acc[o][1] = 0ULL; }

    for (int kk = 0; kk < KKN; kk++) {
        __syncthreads();   // previous GEMM done reading S

        // bilinear setup for own pixel
        float dy = __ldg(offp + (2*kk + 0)*HWI);
        float dx = __ldg(offp + (2*kk + 1)*HWI);
        float py = (float)(h - 1 + kk / 3) + dy;
        float px = (float)(w - 1 + kk % 3) + dx;
        float y0f = floorf(py), x0f = floorf(px);
        float fy = py - y0f, fx = px - x0f;
        int y0 = (int)y0f, x0 = (int)x0f;
        int y1 = y0 + 1,   x1 = x0 + 1;
        float vy0 = (y0 >= 0 && y0 < HI) ? 1.f : 0.f;
        float vy1 = (y1 >= 0 && y1 < HI) ? 1.f : 0.f;
        float vx0 = (x0 >= 0 && x0 < WI) ? 1.f : 0.f;
        float vx1 = (x1 >= 0 && x1 < WI) ? 1.f : 0.f;
        float w00 = (1.f - fy) * (1.f - fx) * vy0 * vx0;
        float w01 = (1.f - fy) * fx         * vy0 * vx1;
        float w10 = fy         * (1.f - fx) * vy1 * vx0;
        float w11 = fy         * fx         * vy1 * vx1;
        int y0c = min(max(y0, 0), HI-1), y1c = min(max(y1, 0), HI-1);
        int x0c = min(max(x0, 0), WI-1), x1c = min(max(x1, 0), WI-1);
        int i00 = y0c*WI + x0c, i01 = y0c*WI + x1c;
        int i10 = y1c*WI + x0c, i11 = y1c*WI + x1c;

        // sample 32 channels -> S[chalf*32 + c][spx]
        #pragma unroll 4
        for (int c = 0; c < 32; c++) {
            const float* xp = xch + c*HWI;
            float s = w00*__ldg(xp + i00) + w01*__ldg(xp + i01)
                    + w10*__ldg(xp + i10) + w11*__ldg(xp + i11);
            Srow[c*64] = s;
        }
        __syncthreads();

        // GEMM: acc[8o][4px] += W[o][c] * S[c][px]
        const float* wk = g_wt + kk*CI*CO + o0;
        #pragma unroll 4
        for (int c = 0; c < CI; c++) {
            ulonglong2 sp = *(const ulonglong2*)(S + c*64 + 4*qb);
            const float* wr = wk + (c << 6);
            float4 wa = __ldg((const float4*)(wr));
            float4 wb = __ldg((const float4*)(wr + 4));
            u64 w2[8];
            w2[0] = pack2(wa.x, wa.x); w2[1] = pack2(wa.y, wa.y);
            w2[2] = pack2(wa.z, wa.z); w2[3] = pack2(wa.w, wa.w);
            w2[4] = pack2(wb.x, wb.x); w2[5] = pack2(wb.y, wb.y);
            w2[6] = pack2(wb.z, wb.z); w2[7] = pack2(wb.w, wb.w);
            #pragma unroll
            for (int o = 0; o < 8; o++) {
                ffma2(acc[o][0], sp.x, w2[o]);
                ffma2(acc[o][1], sp.y, w2[o]);
            }
        }
    }

    // write out: thread's px quad at 4*qb
    #pragma unroll
    for (int o = 0; o < 8; o++) {
        float2 v0 = unpack2(acc[o][0]);
        float2 v1 = unpack2(acc[o][1]);
        float4 v = make_float4(v0.x, v0.y, v1.x, v1.y);
        *(float4*)(out + (b*CO + o0 + o)*HWI + rowoff + 4*qb) = v;
    }
}

// ---------------------------------------------------------------------------
// Launch
// Inputs: x (4*64*128*128), w_off (18*64*9), b_off (18), w_def (64*64*9)
// Output: (4, 64, 128, 128) fp32
// ---------------------------------------------------------------------------
extern "C" void kernel_launch(void* const* d_in, const int* in_sizes, int n_in,
                              void* d_out, int out_size) {
    const float* x     = (const float*)d_in[0];
    const float* w_off = (const float*)d_in[1];
    const float* b_off = (const float*)d_in[2];
    const float* w_def = (const float*)d_in[3];
    float* out = (float*)d_out;

    const int total_px = BI*HWI;  // 65536

    transpose_wdef_kernel<<<(KKN*CI*CO + 255)/256, 256>>>(w_def);
    offset_conv_kernel<<<total_px/256, 256>>>(x, w_off, b_off);
    deform_main_kernel<<<total_px/64, 128>>>(x, out);
}

// round 11
// speedup vs baseline: 1.2763x; 1.1846x over previous
#include <cuda_runtime.h>
#include <cuda_bf16.h>
#include <cstdint>

#define BI 4
#define CI 64
#define HI 128
#define WI 128
#define HWI (HI*WI)
#define JO 18
#define JP 20
#define CO 64
#define KKN 9
#define TPX 128

typedef unsigned long long u64;

__device__ __forceinline__ void ffma2(u64 &d, u64 a, u64 b) {
    asm("fma.rn.f32x2 %0, %1, %2, %0;" : "+l"(d) : "l"(a), "l"(b));
}
__device__ __forceinline__ u64 pack2(float lo, float hi) {
    u64 r; asm("mov.b64 %0, {%1, %2};" : "=l"(r) : "f"(lo), "f"(hi)); return r;
}
__device__ __forceinline__ float2 unpack2(u64 v) {
    float2 r; asm("mov.b64 {%0, %1}, %2;" : "=f"(r.x), "=f"(r.y) : "l"(v)); return r;
}

// Scratch: offsets [b][j][h][w]; channel-paired x [b][c2][p]; weights [kk][c][o]
__device__ float g_off[BI*JO*HWI];
__device__ float2 g_x2[BI*(CI/2)*HWI];   // 16 MB
__device__ float g_wt[KKN*CI*CO];

// ---------------------------------------------------------------------------
// Prep A: pack x channel pairs: g_x2[b][c2][p] = (x[b][2c2][p], x[b][2c2+1][p])
// ---------------------------------------------------------------------------
__global__ void pack_x_kernel(const float* __restrict__ x) {
    int i = blockIdx.x * blockDim.x + threadIdx.x;   // over BI*32*HWI
    if (i < BI*(CI/2)*HWI) {
        int p = i & (HWI-1); int rest = i >> 14;
        int c2 = rest & 31;  int b = rest >> 5;
        const float* src = x + ((size_t)(b*CI + 2*c2))*HWI + p;
        g_x2[i] = make_float2(src[0], src[HWI]);
    }
}

// ---------------------------------------------------------------------------
// Prep B: transpose w_def [o][c][kk] -> g_wt [kk][c][o]
// ---------------------------------------------------------------------------
__global__ void transpose_wdef_kernel(const float* __restrict__ w_def) {
    int i = blockIdx.x * blockDim.x + threadIdx.x;
    if (i < KKN*CI*CO) {
        int o = i & 63; int rest = i >> 6; int c = rest % CI; int kk = rest / CI;
        g_wt[i] = w_def[(o*CI + c)*KKN + kk];
    }
}

// ---------------------------------------------------------------------------
// Kernel 1: offset conv, 1 pixel/thread, packed f32x2 accumulators.
// ---------------------------------------------------------------------------
__global__ __launch_bounds__(256, 4)
void offset_conv_kernel(const float* __restrict__ x,
                        const float* __restrict__ w_off,
                        const float* __restrict__ b_off) {
    __shared__ __align__(16) float ws[KKN*CI*JP];
    int tid = threadIdx.x;
    for (int i = tid; i < KKN*CI*JO; i += blockDim.x) {
        int j = i % JO; int rest = i / JO; int c = rest % CI; int tap = rest / CI;
        ws[(tap*CI + c)*JP + j] = w_off[(j*CI + c)*KKN + tap];
    }
    __syncthreads();

    int p = blockIdx.x * blockDim.x + tid;
    int b = p >> 14, rem = p & (HWI-1);
    int h = rem >> 7, w = rem & (WI-1);
    const float* xb = x + b*CI*HWI;

    u64 acc[9];
    #pragma unroll
    for (int q = 0; q < 9; q++)
        acc[q] = pack2(__ldg(&b_off[2*q]), __ldg(&b_off[2*q+1]));

    for (int tap = 0; tap < KKN; tap++) {
        int ky = tap / 3, kx = tap % 3;
        int y = h - 1 + ky, xx = w - 1 + kx;
        bool v = (y >= 0) & (y < HI) & (xx >= 0) & (xx < WI);
        int idx = y*WI + xx;
        const float* wrow = ws + tap*CI*JP;
        for (int c = 0; c < CI; c++) {
            float a = v ? __ldg(xb + c*HWI + idx) : 0.f;
            u64 a2 = pack2(a, a);
            const ulonglong2* w4 = (const ulonglong2*)(wrow + c*JP);
            #pragma unroll
            for (int q = 0; q < 4; q++) {
                ulonglong2 wv = w4[q];
                ffma2(acc[2*q+0], a2, wv.x);
                ffma2(acc[2*q+1], a2, wv.y);
            }
            u64 w8 = *(const u64*)(wrow + c*JP + 16);
            ffma2(acc[8], a2, w8);
        }
    }
    #pragma unroll
    for (int q = 0; q < 9; q++) {
        float2 vv = unpack2(acc[q]);
        g_off[(b*JO + 2*q+0)*HWI + rem] = vv.x;
        g_off[(b*JO + 2*q+1)*HWI + rem] = vv.y;
    }
}

// ---------------------------------------------------------------------------
// Kernel 2: per-tap im2col + register-blocked GEMM (R6 structure).
// Block = 128 threads = one image row. S[c][128] in smem (32 KB).
// Sampling: channel-PAIR gathers (LDG.64 from g_x2) + paired ffma2 blend.
// GEMM: 8o x 8px FFMA2 tile; weights uniform LDG.128 from g_wt.
// ---------------------------------------------------------------------------
__global__ __launch_bounds__(128, 4)
void deform_main_kernel(float* __restrict__ out) {
    __shared__ __align__(16) float S[CI*TPX];   // 32 KB

    int tid = threadIdx.x;
    int blk = blockIdx.x;
    int b = blk >> 7;
    int h = blk & 127;
    int rowoff = h * WI;
    const float2* x2b = g_x2 + (size_t)b*(CI/2)*HWI;
    int w = tid;
    const float* offp = g_off + b*JO*HWI + rowoff + w;

    int o0 = (tid >> 4) * 8;   // 8 output channels
    int qb = tid & 15;         // quad base: px 4*qb + 64*j

    u64 acc[8][4];
    #pragma unroll
    for (int o = 0; o < 8; o++)
        #pragma unroll
        for (int q = 0; q < 4; q++) acc[o][q] = 0ULL;

    for (int kk = 0; kk < KKN; kk++) {
        __syncthreads();   // previous GEMM done reading S

        // bilinear setup for own pixel
        float dy = __ldg(offp + (2*kk + 0)*HWI);
        float dx = __ldg(offp + (2*kk + 1)*HWI);
        float py = (float)(h - 1 + kk / 3) + dy;
        float px = (float)(w - 1 + kk % 3) + dx;
        float y0f = floorf(py), x0f = floorf(px);
        float fy = py - y0f, fx = px - x0f;
        int y0 = (int)y0f, x0 = (int)x0f;
        int y1 = y0 + 1,   x1 = x0 + 1;
        float vy0 = (y0 >= 0 && y0 < HI) ? 1.f : 0.f;
        float vy1 = (y1 >= 0 && y1 < HI) ? 1.f : 0.f;
        float vx0 = (x0 >= 0 && x0 < WI) ? 1.f : 0.f;
        float vx1 = (x1 >= 0 && x1 < WI) ? 1.f : 0.f;
        float w00 = (1.f - fy) * (1.f - fx) * vy0 * vx0;
        float w01 = (1.f - fy) * fx         * vy0 * vx1;
        float w10 = fy         * (1.f - fx) * vy1 * vx0;
        float w11 = fy         * fx         * vy1 * vx1;
        int y0c = min(max(y0, 0), HI-1), y1c = min(max(y1, 0), HI-1);
        int x0c = min(max(x0, 0), WI-1), x1c = min(max(x1, 0), WI-1);
        int i00 = y0c*WI + x0c, i01 = y0c*WI + x1c;
        int i10 = y1c*WI + x0c, i11 = y1c*WI + x1c;

        u64 W00 = pack2(w00, w00), W01 = pack2(w01, w01);
        u64 W10 = pack2(w10, w10), W11 = pack2(w11, w11);

        // sample channel pairs -> S[2c2][tid], S[2c2+1][tid]
        #pragma unroll 4
        for (int c2 = 0; c2 < CI/2; c2++) {
            const float2* xp = x2b + (size_t)c2*HWI;
            u64 n00 = __ldg((const u64*)(xp + i00));
            u64 n01 = __ldg((const u64*)(xp + i01));
            u64 n10 = __ldg((const u64*)(xp + i10));
            u64 n11 = __ldg((const u64*)(xp + i11));
            u64 s2 = 0ULL;
            ffma2(s2, W00, n00);
            ffma2(s2, W01, n01);
            ffma2(s2, W10, n10);
            ffma2(s2, W11, n11);
            float2 sv = unpack2(s2);
            S[(2*c2+0)*TPX + tid] = sv.x;
            S[(2*c2+1)*TPX + tid] = sv.y;
        }
        __syncthreads();

        // GEMM: acc[8o][8px] += W[o][c] * S[c][px]
        const float* wk = g_wt + kk*CI*CO + o0;
        #pragma unroll 2
        for (int c = 0; c < CI; c++) {
            const float* wr = wk + (c << 6);
            float4 wa = __ldg((const float4*)(wr));
            float4 wb = __ldg((const float4*)(wr + 4));
            u64 w2[8];
            w2[0] = pack2(wa.x, wa.x); w2[1] = pack2(wa.y, wa.y);
            w2[2] = pack2(wa.z, wa.z); w2[3] = pack2(wa.w, wa.w);
            w2[4] = pack2(wb.x, wb.x); w2[5] = pack2(wb.y, wb.y);
            w2[6] = pack2(wb.z, wb.z); w2[7] = pack2(wb.w, wb.w);
            const float* srow = S + c*TPX + 4*qb;
            ulonglong2 sj0 = *(const ulonglong2*)(srow);
            ulonglong2 sj1 = *(const ulonglong2*)(srow + 64);
            #pragma unroll
            for (int o = 0; o < 8; o++) {
                ffma2(acc[o][0], sj0.x, w2[o]);
                ffma2(acc[o][1], sj0.y, w2[o]);
                ffma2(acc[o][2], sj1.x, w2[o]);
                ffma2(acc[o][3], sj1.y, w2[o]);
            }
        }
    }

    // write out: thread's px quads at 4*qb + 64*j
    #pragma unroll
    for (int o = 0; o < 8; o++) {
        float* orow = out + (b*CO + o0 + o)*HWI + rowoff;
        #pragma unroll
        for (int j = 0; j < 2; j++) {
            float2 v0 = unpack2(acc[o][2*j+0]);
            float2 v1 = unpack2(acc[o][2*j+1]);
            float4 v = make_float4(v0.x, v0.y, v1.x, v1.y);
            *(float4*)(orow + 4*qb + 64*j) = v;
        }
    }
}

// ---------------------------------------------------------------------------
// Launch
// Inputs: x (4*64*128*128), w_off (18*64*9), b_off (18), w_def (64*64*9)
// Output: (4, 64, 128, 128) fp32
// ---------------------------------------------------------------------------
extern "C" void kernel_launch(void* const* d_in, const int* in_sizes, int n_in,
                              void* d_out, int out_size) {
    const float* x     = (const float*)d_in[0];
    const float* w_off = (const float*)d_in[1];
    const float* b_off = (const float*)d_in[2];
    const float* w_def = (const float*)d_in[3];
    float* out = (float*)d_out;

    const int total_px = BI*HWI;  // 65536

    pack_x_kernel<<<(BI*(CI/2)*HWI + 255)/256, 256>>>(x);
    transpose_wdef_kernel<<<(KKN*CI*CO + 255)/256, 256>>>(w_def);
    offset_conv_kernel<<<total_px/256, 256>>>(x, w_off, b_off);
    deform_main_kernel<<<total_px/TPX, TPX>>>(out);
}